// round 1
// baseline (speedup 1.0000x reference)
#include <cuda_runtime.h>
#include <math.h>

#define MAXN   50000
#define MAXE   10000
#define MAXNNZ 600000

// ---------------- scratch (static __device__, no allocations) ----------------
__device__ float g_xh[MAXN * 256];    // x @ W1
__device__ float g_he[MAXE * 256];    // hyperedge_attr @ W1
__device__ float g_ax[MAXN * 4];      // per-node attention dot (first half of att)
__device__ float g_ae[MAXE * 4];      // per-edge attention dot (second half)
__device__ float g_alpha[MAXNNZ * 4]; // per-nnz softmax weights (normalized)
__device__ float g_eh[MAXE * 256];    // hyperedge features after propagate 1
__device__ float g_h[MAXN * 256];     // elu(conv1 output)
__device__ float g_xh2[MAXN * 64];    // h @ W2
__device__ float g_eh2[MAXE * 64];    // propagate 1 of conv2
__device__ int g_cntN[MAXN], g_cntE[MAXE];
__device__ int g_curN[MAXN], g_curE[MAXE];
__device__ int g_offN[MAXN + 1], g_offE[MAXE + 1];
__device__ int g_csrN[MAXNNZ], g_csrE[MAXNNZ];

// ---------------- CSR construction ----------------
__global__ void zero_counts_kernel(int N, int E) {
    int i = blockIdx.x * blockDim.x + threadIdx.x;
    int s = gridDim.x * blockDim.x;
    for (int j = i; j < N; j += s) { g_cntN[j] = 0; g_curN[j] = 0; }
    for (int j = i; j < E; j += s) { g_cntE[j] = 0; g_curE[j] = 0; }
}

__global__ void count_kernel(const int* __restrict__ node, const int* __restrict__ hedge, int nnz) {
    int i = blockIdx.x * blockDim.x + threadIdx.x;
    int s = gridDim.x * blockDim.x;
    for (int j = i; j < nnz; j += s) {
        atomicAdd(&g_cntN[node[j]], 1);
        atomicAdd(&g_cntE[hedge[j]], 1);
    }
}

// single-block exclusive scan, shuffle-based (n up to ~64k fine)
__global__ void scan_kernel(const int* __restrict__ cnt, int* __restrict__ off, int n) {
    const int T = 1024;
    int tid = threadIdx.x, lane = tid & 31, warp = tid >> 5;
    __shared__ int wsum[32];
    __shared__ int carry;
    if (tid == 0) carry = 0;
    __syncthreads();
    for (int base = 0; base < n; base += T) {
        int v = (base + tid < n) ? cnt[base + tid] : 0;
        int x = v;
        #pragma unroll
        for (int o = 1; o < 32; o <<= 1) {
            int y = __shfl_up_sync(0xffffffffu, x, o);
            if (lane >= o) x += y;
        }
        if (lane == 31) wsum[warp] = x;
        __syncthreads();
        if (warp == 0) {
            int s2 = wsum[lane];
            #pragma unroll
            for (int o = 1; o < 32; o <<= 1) {
                int y = __shfl_up_sync(0xffffffffu, s2, o);
                if (lane >= o) s2 += y;
            }
            wsum[lane] = s2;
        }
        __syncthreads();
        int add = carry + (warp > 0 ? wsum[warp - 1] : 0);
        if (base + tid < n) off[base + tid] = add + x - v;
        int total = carry + wsum[31];
        __syncthreads();
        if (tid == 0) carry = total;
        __syncthreads();
    }
    if (tid == 0) off[n] = carry;
}

__global__ void scatter_kernel(const int* __restrict__ node, const int* __restrict__ hedge, int nnz) {
    int i = blockIdx.x * blockDim.x + threadIdx.x;
    int s = gridDim.x * blockDim.x;
    for (int j = i; j < nnz; j += s) {
        int pn = g_offN[node[j]] + atomicAdd(&g_curN[node[j]], 1);
        g_csrN[pn] = j;
        int pe = g_offE[hedge[j]] + atomicAdd(&g_curE[hedge[j]], 1);
        g_csrE[pe] = j;
    }
}

// ---------------- tiled fp32 GEMM: C[M,N] = A[M,K] @ B[K,N] ----------------
template <int BM, int BN, int BK, int TM, int TN>
__global__ void sgemm_kernel(const float* __restrict__ A, const float* __restrict__ B,
                             float* __restrict__ C, int M, int N, int K) {
    constexpr int THREADS = (BM / TM) * (BN / TN);
    __shared__ float As[BK][BM];
    __shared__ float Bs[BK][BN];
    int tid = threadIdx.x;
    int tx = tid % (BN / TN);
    int ty = tid / (BN / TN);
    int rowBase = blockIdx.x * BM;
    int colBase = blockIdx.y * BN;
    float acc[TM][TN] = {};
    for (int kt = 0; kt < K; kt += BK) {
        #pragma unroll
        for (int l = tid; l < BM * BK / 4; l += THREADS) {
            int r = l / (BK / 4), c4 = l % (BK / 4);
            int gr = rowBase + r;
            float4 v = make_float4(0.f, 0.f, 0.f, 0.f);
            if (gr < M) v = *(const float4*)&A[gr * K + kt + c4 * 4];
            As[c4 * 4 + 0][r] = v.x;
            As[c4 * 4 + 1][r] = v.y;
            As[c4 * 4 + 2][r] = v.z;
            As[c4 * 4 + 3][r] = v.w;
        }
        #pragma unroll
        for (int l = tid; l < BK * BN / 4; l += THREADS) {
            int r = l / (BN / 4), c4 = l % (BN / 4);
            *(float4*)&Bs[r][c4 * 4] = *(const float4*)&B[(kt + r) * N + colBase + c4 * 4];
        }
        __syncthreads();
        #pragma unroll
        for (int k = 0; k < BK; k++) {
            float ar[TM], br[TN];
            #pragma unroll
            for (int i = 0; i < TM; i++) ar[i] = As[k][ty * TM + i];
            #pragma unroll
            for (int j = 0; j < TN; j++) br[j] = Bs[k][tx * TN + j];
            #pragma unroll
            for (int i = 0; i < TM; i++)
                #pragma unroll
                for (int j = 0; j < TN; j++) acc[i][j] += ar[i] * br[j];
        }
        __syncthreads();
    }
    #pragma unroll
    for (int i = 0; i < TM; i++) {
        int gr = rowBase + ty * TM + i;
        if (gr < M) {
            #pragma unroll
            for (int j4 = 0; j4 < TN / 4; j4++) {
                float4 v = make_float4(acc[i][j4 * 4 + 0], acc[i][j4 * 4 + 1],
                                       acc[i][j4 * 4 + 2], acc[i][j4 * 4 + 3]);
                *(float4*)&C[gr * N + colBase + tx * TN + j4 * 4] = v;
            }
        }
    }
}

// ---------------- attention row-dots: out[n,h] = sum_f src[n, h*64+f] * att[h*128+off+f] ----------------
__global__ void rowdot_kernel(const float* __restrict__ src, const float* __restrict__ att,
                              float* __restrict__ out, int attOff) {
    int n = blockIdx.x;
    int t = threadIdx.x;
    int h = t >> 6, f = t & 63;
    float v = src[n * 256 + t] * att[h * 128 + attOff + f];
    #pragma unroll
    for (int o = 16; o; o >>= 1) v += __shfl_xor_sync(0xffffffffu, v, o);
    __shared__ float w[8];
    if ((t & 31) == 0) w[t >> 5] = v;
    __syncthreads();
    if (t < 4) out[n * 4 + t] = w[2 * t] + w[2 * t + 1];
}

// ---------------- conv1 edge stage: segment softmax + propagate 1 ----------------
__global__ void edge1_kernel(const int* __restrict__ nodeIdx) {
    int e = blockIdx.x;
    int tid = threadIdx.x;
    int lane = tid & 31, warp = tid >> 5;
    int beg = g_offE[e], end = g_offE[e + 1];
    int k = end - beg;
    float aeh[4];
    #pragma unroll
    for (int h = 0; h < 4; h++) aeh[h] = g_ae[e * 4 + h];

    __shared__ float wr[8][4];
    __shared__ float smax[4], sinv[4];

    // phase A1: leaky-relu logits + per-head max
    float lmax[4] = {-1e30f, -1e30f, -1e30f, -1e30f};
    for (int j = tid; j < k; j += 256) {
        int i = g_csrE[beg + j];
        int n = nodeIdx[i];
        #pragma unroll
        for (int h = 0; h < 4; h++) {
            float z = g_ax[n * 4 + h] + aeh[h];
            z = z > 0.f ? z : 0.2f * z;
            g_alpha[i * 4 + h] = z;
            lmax[h] = fmaxf(lmax[h], z);
        }
    }
    #pragma unroll
    for (int o = 16; o; o >>= 1)
        #pragma unroll
        for (int h = 0; h < 4; h++) lmax[h] = fmaxf(lmax[h], __shfl_xor_sync(0xffffffffu, lmax[h], o));
    if (lane == 0) {
        #pragma unroll
        for (int h = 0; h < 4; h++) wr[warp][h] = lmax[h];
    }
    __syncthreads();
    if (tid < 4) {
        float r = wr[0][tid];
        #pragma unroll
        for (int w2 = 1; w2 < 8; w2++) r = fmaxf(r, wr[w2][tid]);
        smax[tid] = r;
    }
    __syncthreads();

    // phase A2: exp + per-head sum
    float lsum[4] = {0.f, 0.f, 0.f, 0.f};
    for (int j = tid; j < k; j += 256) {
        int i = g_csrE[beg + j];
        #pragma unroll
        for (int h = 0; h < 4; h++) {
            float ex = __expf(g_alpha[i * 4 + h] - smax[h]);
            g_alpha[i * 4 + h] = ex;
            lsum[h] += ex;
        }
    }
    #pragma unroll
    for (int o = 16; o; o >>= 1)
        #pragma unroll
        for (int h = 0; h < 4; h++) lsum[h] += __shfl_xor_sync(0xffffffffu, lsum[h], o);
    if (lane == 0) {
        #pragma unroll
        for (int h = 0; h < 4; h++) wr[warp][h] = lsum[h];
    }
    __syncthreads();
    if (tid < 4) {
        float r = wr[0][tid];
        #pragma unroll
        for (int w2 = 1; w2 < 8; w2++) r += wr[w2][tid];
        sinv[tid] = 1.f / (r + 1e-16f);
    }
    __syncthreads();

    // phase A3: normalize alpha (stored for node stage too)
    for (int j = tid; j < k; j += 256) {
        int i = g_csrE[beg + j];
        #pragma unroll
        for (int h = 0; h < 4; h++) g_alpha[i * 4 + h] *= sinv[h];
    }
    __syncthreads();

    // phase B: eh[e,:] = Binv * sum_members alpha * xh[node]
    const int CH = 128;
    __shared__ int snode[CH];
    __shared__ float sal[CH * 4];
    float Binv = k > 0 ? 1.f / (float)k : 0.f;
    int g = tid >> 6, f4 = tid & 63, h = f4 >> 4;
    float4 acc = make_float4(0.f, 0.f, 0.f, 0.f);
    const float4* xh4 = (const float4*)g_xh;
    for (int base = 0; base < k; base += CH) {
        int c = min(CH, k - base);
        __syncthreads();
        if (tid < c) {
            int i = g_csrE[beg + base + tid];
            snode[tid] = nodeIdx[i];
            ((float4*)sal)[tid] = ((const float4*)g_alpha)[i];
        }
        __syncthreads();
        for (int j = g; j < c; j += 4) {
            float a = sal[j * 4 + h];
            float4 xv = xh4[snode[j] * 64 + f4];
            acc.x += a * xv.x; acc.y += a * xv.y; acc.z += a * xv.z; acc.w += a * xv.w;
        }
    }
    __shared__ float4 racc[256];
    racc[tid] = acc;
    __syncthreads();
    if (tid < 64) {
        float4 a = racc[tid], b = racc[tid + 64], c2 = racc[tid + 128], d2 = racc[tid + 192];
        float4 r;
        r.x = (a.x + b.x + c2.x + d2.x) * Binv;
        r.y = (a.y + b.y + c2.y + d2.y) * Binv;
        r.z = (a.z + b.z + c2.z + d2.z) * Binv;
        r.w = (a.w + b.w + c2.w + d2.w) * Binv;
        ((float4*)g_eh)[e * 64 + tid] = r;
    }
}

__device__ __forceinline__ float eluf(float x) { return x > 0.f ? x : expm1f(x); }

// ---------------- conv1 node stage: propagate 2 + bias + elu ----------------
__global__ void node1_kernel(const int* __restrict__ hedgeIdx, const float* __restrict__ b1) {
    int n = blockIdx.x;
    int tid = threadIdx.x;
    int beg = g_offN[n], end = g_offN[n + 1];
    int d = end - beg;
    float Dinv = d > 0 ? 1.f / (float)d : 0.f;
    int g = tid >> 6, f4 = tid & 63, h = f4 >> 4;
    float4 acc = make_float4(0.f, 0.f, 0.f, 0.f);
    const float4* eh4 = (const float4*)g_eh;
    for (int j = beg + g; j < end; j += 4) {
        int i = g_csrN[j];
        int e = hedgeIdx[i];
        float a = g_alpha[i * 4 + h];
        float4 ev = eh4[e * 64 + f4];
        acc.x += a * ev.x; acc.y += a * ev.y; acc.z += a * ev.z; acc.w += a * ev.w;
    }
    __shared__ float4 racc[256];
    racc[tid] = acc;
    __syncthreads();
    if (tid < 64) {
        float4 a = racc[tid], b = racc[tid + 64], c2 = racc[tid + 128], d2 = racc[tid + 192];
        float4 bv = ((const float4*)b1)[tid];
        float4 r;
        r.x = eluf((a.x + b.x + c2.x + d2.x) * Dinv + bv.x);
        r.y = eluf((a.y + b.y + c2.y + d2.y) * Dinv + bv.y);
        r.z = eluf((a.z + b.z + c2.z + d2.z) * Dinv + bv.z);
        r.w = eluf((a.w + b.w + c2.w + d2.w) * Dinv + bv.w);
        ((float4*)g_h)[n * 64 + tid] = r;
    }
}

// ---------------- conv2 (no attention, F=64) ----------------
__global__ void edge2_kernel(const int* __restrict__ nodeIdx) {
    int e = blockIdx.x;
    int tid = threadIdx.x;
    int beg = g_offE[e], end = g_offE[e + 1];
    int k = end - beg;
    float Binv = k > 0 ? 1.f / (float)k : 0.f;
    int g = tid >> 6, f = tid & 63;
    float acc = 0.f;
    for (int j = beg + g; j < end; j += 4) {
        int i = g_csrE[j];
        int n = nodeIdx[i];
        acc += g_xh2[n * 64 + f];
    }
    __shared__ float racc[256];
    racc[tid] = acc;
    __syncthreads();
    if (tid < 64)
        g_eh2[e * 64 + tid] = (racc[tid] + racc[tid + 64] + racc[tid + 128] + racc[tid + 192]) * Binv;
}

__global__ void node2_kernel(const int* __restrict__ hedgeIdx, const float* __restrict__ b2,
                             float* __restrict__ out) {
    int n = blockIdx.x;
    int tid = threadIdx.x;
    int beg = g_offN[n], end = g_offN[n + 1];
    int d = end - beg;
    float Dinv = d > 0 ? 1.f / (float)d : 0.f;
    int g = tid >> 6, f = tid & 63;
    float acc = 0.f;
    for (int j = beg + g; j < end; j += 4) {
        int i = g_csrN[j];
        int e = hedgeIdx[i];
        acc += g_eh2[e * 64 + f];
    }
    __shared__ float racc[256];
    racc[tid] = acc;
    __syncthreads();
    if (tid < 64)
        out[n * 64 + tid] =
            (racc[tid] + racc[tid + 64] + racc[tid + 128] + racc[tid + 192]) * Dinv + b2[tid];
}

// ---------------- launch ----------------
extern "C" void kernel_launch(void* const* d_in, const int* in_sizes, int n_in,
                              void* d_out, int out_size) {
    const float* x    = (const float*)d_in[0];
    const int*   ei   = (const int*)d_in[1];
    const float* hat  = (const float*)d_in[2];
    const float* W1   = (const float*)d_in[3];
    const float* att1 = (const float*)d_in[4];
    const float* b1   = (const float*)d_in[5];
    const float* W2   = (const float*)d_in[6];
    const float* b2   = (const float*)d_in[7];
    float* out = (float*)d_out;

    int N   = in_sizes[0] / 128;
    int NNZ = in_sizes[1] / 2;
    int E   = in_sizes[2] / 128;
    const int* node  = ei;
    const int* hedge = ei + NNZ;

    float *p_xh, *p_he, *p_h, *p_xh2, *p_ax, *p_ae;
    int *p_cntN, *p_cntE, *p_offN, *p_offE;
    cudaGetSymbolAddress((void**)&p_xh, g_xh);
    cudaGetSymbolAddress((void**)&p_he, g_he);
    cudaGetSymbolAddress((void**)&p_h, g_h);
    cudaGetSymbolAddress((void**)&p_xh2, g_xh2);
    cudaGetSymbolAddress((void**)&p_ax, g_ax);
    cudaGetSymbolAddress((void**)&p_ae, g_ae);
    cudaGetSymbolAddress((void**)&p_cntN, g_cntN);
    cudaGetSymbolAddress((void**)&p_cntE, g_cntE);
    cudaGetSymbolAddress((void**)&p_offN, g_offN);
    cudaGetSymbolAddress((void**)&p_offE, g_offE);

    // CSR build
    zero_counts_kernel<<<128, 256>>>(N, E);
    count_kernel<<<480, 256>>>(node, hedge, NNZ);
    scan_kernel<<<1, 1024>>>(p_cntE, p_offE, E);
    scan_kernel<<<1, 1024>>>(p_cntN, p_offN, N);
    scatter_kernel<<<480, 256>>>(node, hedge, NNZ);

    // GEMMs for conv1 features
    sgemm_kernel<128, 128, 16, 8, 8><<<dim3((N + 127) / 128, 2), 256>>>(x, W1, p_xh, N, 256, 128);
    sgemm_kernel<128, 128, 16, 8, 8><<<dim3((E + 127) / 128, 2), 256>>>(hat, W1, p_he, E, 256, 128);

    // attention dots
    rowdot_kernel<<<N, 256>>>(p_xh, att1, p_ax, 0);
    rowdot_kernel<<<E, 256>>>(p_he, att1, p_ae, 64);

    // conv1: softmax + two propagates + elu
    edge1_kernel<<<E, 256>>>(node);
    node1_kernel<<<N, 256>>>(hedge, b1);

    // conv2
    sgemm_kernel<128, 64, 16, 8, 4><<<dim3((N + 127) / 128, 1), 256>>>(p_h, W2, p_xh2, N, 64, 256);
    edge2_kernel<<<E, 256>>>(node);
    node2_kernel<<<N, 256>>>(hedge, b2, out);
}

// round 2
// speedup vs baseline: 1.1573x; 1.1573x over previous
#include <cuda_runtime.h>
#include <math.h>

#define MAXN   50000
#define MAXE   10000
#define MAXNNZ 600000

// ---------------- scratch (static __device__, no allocations) ----------------
__device__ float g_xh[MAXN * 256];    // x @ W1
__device__ float g_he[MAXE * 256];    // hyperedge_attr @ W1
__device__ float g_ax[MAXN * 4];      // per-node attention dot (first half of att)
__device__ float g_ae[MAXE * 4];      // per-edge attention dot (second half)
__device__ float g_alpha[MAXNNZ * 4]; // per-nnz softmax weights (normalized)
__device__ float g_eh[MAXE * 256];    // hyperedge features after propagate 1
__device__ float g_h[MAXN * 256];     // elu(conv1 output)
__device__ float g_xh2[MAXN * 64];    // h @ W2
__device__ float g_eh2[MAXE * 64];    // propagate 1 of conv2
__device__ int g_cntN[MAXN], g_cntE[MAXE];
__device__ int g_curN[MAXN], g_curE[MAXE];
__device__ int g_offN[MAXN], g_offE[MAXE];
__device__ int g_csrN[MAXNNZ], g_csrE[MAXNNZ];
__device__ int g_totN, g_totE;

// ---------------- CSR construction ----------------
__global__ void zero_counts_kernel(int N, int E) {
    int i = blockIdx.x * blockDim.x + threadIdx.x;
    int s = gridDim.x * blockDim.x;
    if (i == 0) { g_totN = 0; g_totE = 0; }
    for (int j = i; j < N; j += s) { g_cntN[j] = 0; g_curN[j] = 0; }
    for (int j = i; j < E; j += s) { g_cntE[j] = 0; g_curE[j] = 0; }
}

__global__ void count_kernel(const int* __restrict__ node, const int* __restrict__ hedge, int nnz) {
    int i = blockIdx.x * blockDim.x + threadIdx.x;
    int s = gridDim.x * blockDim.x;
    for (int j = i; j < nnz; j += s) {
        atomicAdd(&g_cntN[node[j]], 1);
        atomicAdd(&g_cntE[hedge[j]], 1);
    }
}

// Allocate contiguous (unordered) segment bases: warp-aggregated atomicAdd.
// Segment placement order is irrelevant to the result (each segment sums its
// own members); only contiguity matters.
__device__ __forceinline__ void alloc_ranges(const int* __restrict__ cnt, int* __restrict__ off,
                                             int* total, int n, int gwarp, int nwarps, int lane) {
    for (int j0 = gwarp * 32; j0 < n; j0 += nwarps * 32) {
        int j = j0 + lane;
        int c = (j < n) ? cnt[j] : 0;
        int x = c;
        #pragma unroll
        for (int o = 1; o < 32; o <<= 1) {
            int y = __shfl_up_sync(0xffffffffu, x, o);
            if (lane >= o) x += y;
        }
        int wtot = __shfl_sync(0xffffffffu, x, 31);
        int base = 0;
        if (lane == 0) base = atomicAdd(total, wtot);
        base = __shfl_sync(0xffffffffu, base, 0);
        if (j < n) off[j] = base + x - c;
    }
}

__global__ void alloc_kernel(int N, int E) {
    int t = blockIdx.x * blockDim.x + threadIdx.x;
    int gwarp = t >> 5, lane = t & 31;
    int nwarps = (gridDim.x * blockDim.x) >> 5;
    alloc_ranges(g_cntN, g_offN, &g_totN, N, gwarp, nwarps, lane);
    alloc_ranges(g_cntE, g_offE, &g_totE, E, gwarp, nwarps, lane);
}

__global__ void scatter_kernel(const int* __restrict__ node, const int* __restrict__ hedge, int nnz) {
    int i = blockIdx.x * blockDim.x + threadIdx.x;
    int s = gridDim.x * blockDim.x;
    for (int j = i; j < nnz; j += s) {
        int pn = g_offN[node[j]] + atomicAdd(&g_curN[node[j]], 1);
        g_csrN[pn] = j;
        int pe = g_offE[hedge[j]] + atomicAdd(&g_curE[hedge[j]], 1);
        g_csrE[pe] = j;
    }
}

// ---------------- tiled fp32 GEMM: C[M,N] = A[M,K] @ B[K,N] ----------------
template <int BM, int BN, int BK, int TM, int TN>
__global__ __launch_bounds__(256) void sgemm_kernel(const float* __restrict__ A,
                                                    const float* __restrict__ B,
                                                    float* __restrict__ C, int M, int N, int K) {
    constexpr int THREADS = (BM / TM) * (BN / TN);
    __shared__ float As[BK][BM];
    __shared__ float Bs[BK][BN];
    int tid = threadIdx.x;
    int tx = tid % (BN / TN);
    int ty = tid / (BN / TN);
    int rowBase = blockIdx.x * BM;
    int colBase = blockIdx.y * BN;
    float acc[TM][TN] = {};
    for (int kt = 0; kt < K; kt += BK) {
        #pragma unroll
        for (int l = tid; l < BM * BK / 4; l += THREADS) {
            int r = l / (BK / 4), c4 = l % (BK / 4);
            int gr = rowBase + r;
            float4 v = make_float4(0.f, 0.f, 0.f, 0.f);
            if (gr < M) v = *(const float4*)&A[gr * K + kt + c4 * 4];
            As[c4 * 4 + 0][r] = v.x;
            As[c4 * 4 + 1][r] = v.y;
            As[c4 * 4 + 2][r] = v.z;
            As[c4 * 4 + 3][r] = v.w;
        }
        #pragma unroll
        for (int l = tid; l < BK * BN / 4; l += THREADS) {
            int r = l / (BN / 4), c4 = l % (BN / 4);
            *(float4*)&Bs[r][c4 * 4] = *(const float4*)&B[(kt + r) * N + colBase + c4 * 4];
        }
        __syncthreads();
        #pragma unroll
        for (int k = 0; k < BK; k++) {
            float ar[TM], br[TN];
            #pragma unroll
            for (int i = 0; i < TM; i++) ar[i] = As[k][ty * TM + i];
            #pragma unroll
            for (int j = 0; j < TN; j++) br[j] = Bs[k][tx * TN + j];
            #pragma unroll
            for (int i = 0; i < TM; i++)
                #pragma unroll
                for (int j = 0; j < TN; j++) acc[i][j] += ar[i] * br[j];
        }
        __syncthreads();
    }
    #pragma unroll
    for (int i = 0; i < TM; i++) {
        int gr = rowBase + ty * TM + i;
        if (gr < M) {
            #pragma unroll
            for (int j4 = 0; j4 < TN / 4; j4++) {
                float4 v = make_float4(acc[i][j4 * 4 + 0], acc[i][j4 * 4 + 1],
                                       acc[i][j4 * 4 + 2], acc[i][j4 * 4 + 3]);
                *(float4*)&C[gr * N + colBase + tx * TN + j4 * 4] = v;
            }
        }
    }
}

// ---------------- attention row-dots ----------------
__global__ void rowdot_kernel(const float* __restrict__ src, const float* __restrict__ att,
                              float* __restrict__ out, int attOff) {
    int n = blockIdx.x;
    int t = threadIdx.x;
    int h = t >> 6, f = t & 63;
    float v = src[n * 256 + t] * att[h * 128 + attOff + f];
    #pragma unroll
    for (int o = 16; o; o >>= 1) v += __shfl_xor_sync(0xffffffffu, v, o);
    __shared__ float w[8];
    if ((t & 31) == 0) w[t >> 5] = v;
    __syncthreads();
    if (t < 4) out[n * 4 + t] = w[2 * t] + w[2 * t + 1];
}

// ---------------- conv1 edge stage: segment softmax + propagate 1 ----------------
#define ECAP 1024
__global__ __launch_bounds__(256) void edge1_kernel(const int* __restrict__ nodeIdx) {
    int e = blockIdx.x;
    int tid = threadIdx.x;
    int lane = tid & 31, warp = tid >> 5;
    int beg = g_offE[e];
    int k = g_cntE[e];
    float aeh[4];
    #pragma unroll
    for (int h = 0; h < 4; h++) aeh[h] = g_ae[e * 4 + h];

    __shared__ int snode[ECAP];
    __shared__ int sidx[ECAP];
    __shared__ float slog[ECAP * 4];
    __shared__ float4 racc[256];
    __shared__ float wr[8][4];
    __shared__ float smax[4], sinv[4];

    int g = tid >> 6, f4 = tid & 63, hh = f4 >> 4;
    float Binv = k > 0 ? 1.f / (float)k : 0.f;
    float4 acc = make_float4(0.f, 0.f, 0.f, 0.f);
    const float4* xh4 = (const float4*)g_xh;

    if (k <= ECAP) {
        // ---- fast path: whole segment staged in smem ----
        float lmax[4] = {-1e30f, -1e30f, -1e30f, -1e30f};
        for (int j = tid; j < k; j += 256) {
            int i = g_csrE[beg + j];
            int n = nodeIdx[i];
            sidx[j] = i;
            snode[j] = n;
            #pragma unroll
            for (int h = 0; h < 4; h++) {
                float z = g_ax[n * 4 + h] + aeh[h];
                z = z > 0.f ? z : 0.2f * z;
                slog[j * 4 + h] = z;
                lmax[h] = fmaxf(lmax[h], z);
            }
        }
        #pragma unroll
        for (int o = 16; o; o >>= 1)
            #pragma unroll
            for (int h = 0; h < 4; h++)
                lmax[h] = fmaxf(lmax[h], __shfl_xor_sync(0xffffffffu, lmax[h], o));
        if (lane == 0)
            #pragma unroll
            for (int h = 0; h < 4; h++) wr[warp][h] = lmax[h];
        __syncthreads();
        if (tid < 4) {
            float r = wr[0][tid];
            #pragma unroll
            for (int w2 = 1; w2 < 8; w2++) r = fmaxf(r, wr[w2][tid]);
            smax[tid] = r;
        }
        __syncthreads();

        float lsum[4] = {0.f, 0.f, 0.f, 0.f};
        for (int j = tid; j < k; j += 256) {
            #pragma unroll
            for (int h = 0; h < 4; h++) {
                float ex = __expf(slog[j * 4 + h] - smax[h]);
                slog[j * 4 + h] = ex;
                lsum[h] += ex;
            }
        }
        #pragma unroll
        for (int o = 16; o; o >>= 1)
            #pragma unroll
            for (int h = 0; h < 4; h++) lsum[h] += __shfl_xor_sync(0xffffffffu, lsum[h], o);
        if (lane == 0)
            #pragma unroll
            for (int h = 0; h < 4; h++) wr[warp][h] = lsum[h];
        __syncthreads();
        if (tid < 4) {
            float r = wr[0][tid];
            #pragma unroll
            for (int w2 = 1; w2 < 8; w2++) r += wr[w2][tid];
            sinv[tid] = 1.f / (r + 1e-16f);
        }
        __syncthreads();

        // normalize in smem + single global write of alpha (node1 needs it)
        for (int j = tid; j < k; j += 256) {
            float4 a;
            a.x = slog[j * 4 + 0] * sinv[0];
            a.y = slog[j * 4 + 1] * sinv[1];
            a.z = slog[j * 4 + 2] * sinv[2];
            a.w = slog[j * 4 + 3] * sinv[3];
            slog[j * 4 + 0] = a.x; slog[j * 4 + 1] = a.y;
            slog[j * 4 + 2] = a.z; slog[j * 4 + 3] = a.w;
            ((float4*)g_alpha)[sidx[j]] = a;
        }
        __syncthreads();

        // propagate 1 straight from smem
        for (int j = g; j < k; j += 4) {
            float a = slog[j * 4 + hh];
            float4 xv = xh4[snode[j] * 64 + f4];
            acc.x += a * xv.x; acc.y += a * xv.y; acc.z += a * xv.z; acc.w += a * xv.w;
        }
    } else {
        // ---- fallback: global alpha staging (k > ECAP) ----
        float lmax[4] = {-1e30f, -1e30f, -1e30f, -1e30f};
        for (int j = tid; j < k; j += 256) {
            int i = g_csrE[beg + j];
            int n = nodeIdx[i];
            #pragma unroll
            for (int h = 0; h < 4; h++) {
                float z = g_ax[n * 4 + h] + aeh[h];
                z = z > 0.f ? z : 0.2f * z;
                g_alpha[i * 4 + h] = z;
                lmax[h] = fmaxf(lmax[h], z);
            }
        }
        #pragma unroll
        for (int o = 16; o; o >>= 1)
            #pragma unroll
            for (int h = 0; h < 4; h++)
                lmax[h] = fmaxf(lmax[h], __shfl_xor_sync(0xffffffffu, lmax[h], o));
        if (lane == 0)
            #pragma unroll
            for (int h = 0; h < 4; h++) wr[warp][h] = lmax[h];
        __syncthreads();
        if (tid < 4) {
            float r = wr[0][tid];
            #pragma unroll
            for (int w2 = 1; w2 < 8; w2++) r = fmaxf(r, wr[w2][tid]);
            smax[tid] = r;
        }
        __syncthreads();
        float lsum[4] = {0.f, 0.f, 0.f, 0.f};
        for (int j = tid; j < k; j += 256) {
            int i = g_csrE[beg + j];
            #pragma unroll
            for (int h = 0; h < 4; h++) {
                float ex = __expf(g_alpha[i * 4 + h] - smax[h]);
                g_alpha[i * 4 + h] = ex;
                lsum[h] += ex;
            }
        }
        #pragma unroll
        for (int o = 16; o; o >>= 1)
            #pragma unroll
            for (int h = 0; h < 4; h++) lsum[h] += __shfl_xor_sync(0xffffffffu, lsum[h], o);
        if (lane == 0)
            #pragma unroll
            for (int h = 0; h < 4; h++) wr[warp][h] = lsum[h];
        __syncthreads();
        if (tid < 4) {
            float r = wr[0][tid];
            #pragma unroll
            for (int w2 = 1; w2 < 8; w2++) r += wr[w2][tid];
            sinv[tid] = 1.f / (r + 1e-16f);
        }
        __syncthreads();
        for (int j = tid; j < k; j += 256) {
            int i = g_csrE[beg + j];
            #pragma unroll
            for (int h = 0; h < 4; h++) g_alpha[i * 4 + h] *= sinv[h];
        }
        __syncthreads();
        // chunked propagate 1 (reuse smem buffers)
        for (int base = 0; base < k; base += ECAP) {
            int c = min(ECAP, k - base);
            __syncthreads();
            for (int j = tid; j < c; j += 256) {
                int i = g_csrE[beg + base + j];
                snode[j] = nodeIdx[i];
                ((float4*)slog)[j] = ((const float4*)g_alpha)[i];
            }
            __syncthreads();
            for (int j = g; j < c; j += 4) {
                float a = slog[j * 4 + hh];
                float4 xv = xh4[snode[j] * 64 + f4];
                acc.x += a * xv.x; acc.y += a * xv.y; acc.z += a * xv.z; acc.w += a * xv.w;
            }
        }
    }

    racc[tid] = acc;
    __syncthreads();
    if (tid < 64) {
        float4 a = racc[tid], b = racc[tid + 64], c2 = racc[tid + 128], d2 = racc[tid + 192];
        float4 r;
        r.x = (a.x + b.x + c2.x + d2.x) * Binv;
        r.y = (a.y + b.y + c2.y + d2.y) * Binv;
        r.z = (a.z + b.z + c2.z + d2.z) * Binv;
        r.w = (a.w + b.w + c2.w + d2.w) * Binv;
        ((float4*)g_eh)[e * 64 + tid] = r;
    }
}

__device__ __forceinline__ float eluf(float x) { return x > 0.f ? x : expm1f(x); }

// ---------------- conv1 node stage: propagate 2 + bias + elu ----------------
__global__ __launch_bounds__(256) void node1_kernel(const int* __restrict__ hedgeIdx,
                                                    const float* __restrict__ b1) {
    int n = blockIdx.x;
    int tid = threadIdx.x;
    int beg = g_offN[n];
    int d = g_cntN[n];
    int end = beg + d;
    float Dinv = d > 0 ? 1.f / (float)d : 0.f;
    int g = tid >> 6, f4 = tid & 63, h = f4 >> 4;
    float4 acc = make_float4(0.f, 0.f, 0.f, 0.f);
    const float4* eh4 = (const float4*)g_eh;
    for (int j = beg + g; j < end; j += 4) {
        int i = g_csrN[j];
        int e = hedgeIdx[i];
        float a = g_alpha[i * 4 + h];
        float4 ev = eh4[e * 64 + f4];
        acc.x += a * ev.x; acc.y += a * ev.y; acc.z += a * ev.z; acc.w += a * ev.w;
    }
    __shared__ float4 racc[256];
    racc[tid] = acc;
    __syncthreads();
    if (tid < 64) {
        float4 a = racc[tid], b = racc[tid + 64], c2 = racc[tid + 128], d2 = racc[tid + 192];
        float4 bv = ((const float4*)b1)[tid];
        float4 r;
        r.x = eluf((a.x + b.x + c2.x + d2.x) * Dinv + bv.x);
        r.y = eluf((a.y + b.y + c2.y + d2.y) * Dinv + bv.y);
        r.z = eluf((a.z + b.z + c2.z + d2.z) * Dinv + bv.z);
        r.w = eluf((a.w + b.w + c2.w + d2.w) * Dinv + bv.w);
        ((float4*)g_h)[n * 64 + tid] = r;
    }
}

// ---------------- conv2 (no attention, F=64) ----------------
__global__ __launch_bounds__(256) void edge2_kernel(const int* __restrict__ nodeIdx) {
    int e = blockIdx.x;
    int tid = threadIdx.x;
    int beg = g_offE[e];
    int k = g_cntE[e];
    int end = beg + k;
    float Binv = k > 0 ? 1.f / (float)k : 0.f;
    int g = tid >> 6, f = tid & 63;
    float acc = 0.f;
    for (int j = beg + g; j < end; j += 4) {
        int i = g_csrE[j];
        int n = nodeIdx[i];
        acc += g_xh2[n * 64 + f];
    }
    __shared__ float racc[256];
    racc[tid] = acc;
    __syncthreads();
    if (tid < 64)
        g_eh2[e * 64 + tid] = (racc[tid] + racc[tid + 64] + racc[tid + 128] + racc[tid + 192]) * Binv;
}

__global__ __launch_bounds__(256) void node2_kernel(const int* __restrict__ hedgeIdx,
                                                    const float* __restrict__ b2,
                                                    float* __restrict__ out) {
    int n = blockIdx.x;
    int tid = threadIdx.x;
    int beg = g_offN[n];
    int d = g_cntN[n];
    int end = beg + d;
    float Dinv = d > 0 ? 1.f / (float)d : 0.f;
    int g = tid >> 6, f = tid & 63;
    float acc = 0.f;
    for (int j = beg + g; j < end; j += 4) {
        int i = g_csrN[j];
        int e = hedgeIdx[i];
        acc += g_eh2[e * 64 + f];
    }
    __shared__ float racc[256];
    racc[tid] = acc;
    __syncthreads();
    if (tid < 64)
        out[n * 64 + tid] =
            (racc[tid] + racc[tid + 64] + racc[tid + 128] + racc[tid + 192]) * Dinv + b2[tid];
}

// ---------------- launch ----------------
extern "C" void kernel_launch(void* const* d_in, const int* in_sizes, int n_in,
                              void* d_out, int out_size) {
    const float* x    = (const float*)d_in[0];
    const int*   ei   = (const int*)d_in[1];
    const float* hat  = (const float*)d_in[2];
    const float* W1   = (const float*)d_in[3];
    const float* att1 = (const float*)d_in[4];
    const float* b1   = (const float*)d_in[5];
    const float* W2   = (const float*)d_in[6];
    const float* b2   = (const float*)d_in[7];
    float* out = (float*)d_out;

    int N   = in_sizes[0] / 128;
    int NNZ = in_sizes[1] / 2;
    int E   = in_sizes[2] / 128;
    const int* node  = ei;
    const int* hedge = ei + NNZ;

    float *p_xh, *p_he, *p_h, *p_xh2, *p_ax, *p_ae;
    cudaGetSymbolAddress((void**)&p_xh, g_xh);
    cudaGetSymbolAddress((void**)&p_he, g_he);
    cudaGetSymbolAddress((void**)&p_h, g_h);
    cudaGetSymbolAddress((void**)&p_xh2, g_xh2);
    cudaGetSymbolAddress((void**)&p_ax, g_ax);
    cudaGetSymbolAddress((void**)&p_ae, g_ae);

    // CSR build (unordered contiguous ranges — no prefix scan needed)
    zero_counts_kernel<<<128, 256>>>(N, E);
    count_kernel<<<480, 256>>>(node, hedge, NNZ);
    alloc_kernel<<<64, 256>>>(N, E);
    scatter_kernel<<<480, 256>>>(node, hedge, NNZ);

    // GEMMs for conv1 features
    sgemm_kernel<128, 128, 16, 8, 8><<<dim3((N + 127) / 128, 2), 256>>>(x, W1, p_xh, N, 256, 128);
    sgemm_kernel<128, 128, 16, 8, 8><<<dim3((E + 127) / 128, 2), 256>>>(hat, W1, p_he, E, 256, 128);

    // attention dots
    rowdot_kernel<<<N, 256>>>(p_xh, att1, p_ax, 0);
    rowdot_kernel<<<E, 256>>>(p_he, att1, p_ae, 64);

    // conv1: softmax + two propagates + elu
    edge1_kernel<<<E, 256>>>(node);
    node1_kernel<<<N, 256>>>(hedge, b1);

    // conv2
    sgemm_kernel<128, 64, 16, 8, 4><<<dim3((N + 127) / 128, 1), 256>>>(p_h, W2, p_xh2, N, 64, 256);
    edge2_kernel<<<E, 256>>>(node);
    node2_kernel<<<N, 256>>>(hedge, b2, out);
}